// round 1
// baseline (speedup 1.0000x reference)
#include <cuda_runtime.h>
#include <math.h>

#define NN 100000
#define EE 3200000
#define GG 1024

// ---------------- scratch (no allocations allowed) ----------------
__device__ float g_z[NN * 64];       // z = X @ W1 (then overwritten by u = relu(z+agg+b1))
__device__ float g_agg[NN * 64];     // edge aggregation accumulator
__device__ float g_h[NN * 64];       // layer-0 output
__device__ float g_stats[128];       // [0:64) sum, [64:128) sumsq
__device__ float g_W2p[64 * 64];     // BN-folded W2
__device__ float g_b2p[64];          // BN-folded b2

// ---------------- GEMM: out[n,64] = X[n,K] @ W[K,64] (+bias, +relu) ----------------
template <int K, bool RELU, bool BIAS>
__global__ __launch_bounds__(256) void gemm64(const float* __restrict__ X,
                                              const float* __restrict__ W,
                                              const float* __restrict__ bias,
                                              float* __restrict__ out, int n) {
    __shared__ float Xs[64][68];   // padded: avoid bank conflicts on column reads
    __shared__ float Ws[64][64];
    const int tid  = threadIdx.x;
    const int row0 = blockIdx.x * 64;
    const int col4 = (tid & 15) * 4;
    const int row4 = (tid >> 4) * 4;

    float acc[4][4];
#pragma unroll
    for (int r = 0; r < 4; r++)
#pragma unroll
        for (int c = 0; c < 4; c++) acc[r][c] = 0.f;

    for (int k0 = 0; k0 < K; k0 += 64) {
        // stage 64x64 X tile
#pragma unroll
        for (int t = 0; t < 4; t++) {
            int fidx = t * 256 + tid;
            int r = fidx >> 4;
            int c = (fidx & 15) * 4;
            float4 v = make_float4(0.f, 0.f, 0.f, 0.f);
            int row = row0 + r;
            if (row < n) v = *(const float4*)(X + (size_t)row * K + k0 + c);
            *(float4*)&Xs[r][c] = v;
        }
        // stage 64x64 W tile
#pragma unroll
        for (int t = 0; t < 4; t++) {
            int fidx = t * 256 + tid;
            int kk = fidx >> 4;
            int c = (fidx & 15) * 4;
            *(float4*)&Ws[kk][c] = *(const float4*)(W + (size_t)(k0 + kk) * 64 + c);
        }
        __syncthreads();
#pragma unroll 16
        for (int kk = 0; kk < 64; kk++) {
            float4 wv = *(float4*)&Ws[kk][col4];
#pragma unroll
            for (int r = 0; r < 4; r++) {
                float xv = Xs[row4 + r][kk];
                acc[r][0] += xv * wv.x;
                acc[r][1] += xv * wv.y;
                acc[r][2] += xv * wv.z;
                acc[r][3] += xv * wv.w;
            }
        }
        __syncthreads();
    }
#pragma unroll
    for (int r = 0; r < 4; r++) {
        int row = row0 + row4 + r;
        if (row < n) {
            float4 o = make_float4(acc[r][0], acc[r][1], acc[r][2], acc[r][3]);
            if (BIAS) {
                o.x += bias[col4 + 0];
                o.y += bias[col4 + 1];
                o.z += bias[col4 + 2];
                o.w += bias[col4 + 3];
            }
            if (RELU) {
                o.x = fmaxf(o.x, 0.f);
                o.y = fmaxf(o.y, 0.f);
                o.z = fmaxf(o.z, 0.f);
                o.w = fmaxf(o.w, 0.f);
            }
            *(float4*)(out + (size_t)row * 64 + col4) = o;
        }
    }
}

// ---------------- edge scatter-add: agg[dst] += z[src], 64 feats ----------------
__global__ __launch_bounds__(256) void edge_agg(const int* __restrict__ src,
                                                const int* __restrict__ dst,
                                                const float* __restrict__ z,
                                                float* __restrict__ agg) {
    long long idx = (long long)blockIdx.x * 256 + threadIdx.x;  // over EE*16
    int e = (int)(idx >> 4);
    if (e >= EE) return;
    int c = ((int)idx & 15) * 4;
    int s = __ldg(src + e);
    int d = __ldg(dst + e);
    float4 v = *(const float4*)(z + (size_t)s * 64 + c);
    float* a = agg + (size_t)d * 64 + c;
    atomicAdd(a + 0, v.x);
    atomicAdd(a + 1, v.y);
    atomicAdd(a + 2, v.z);
    atomicAdd(a + 3, v.w);
}

// ---------------- fused: u = relu(z + agg + b1); channel sum/sumsq ----------------
__global__ __launch_bounds__(256) void postagg(float* __restrict__ z,
                                               const float* __restrict__ agg,
                                               const float* __restrict__ b1, int n) {
    const int f = threadIdx.x & 63;
    const int ty = threadIdx.x >> 6;
    const float b = b1[f];
    float s = 0.f, s2 = 0.f;
    for (int i = blockIdx.x * 4 + ty; i < n; i += gridDim.x * 4) {
        size_t o = (size_t)i * 64 + f;
        float u = fmaxf(z[o] + agg[o] + b, 0.f);
        z[o] = u;
        s += u;
        s2 += u * u;
    }
    __shared__ float ss[4][64], ss2[4][64];
    ss[ty][f] = s;
    ss2[ty][f] = s2;
    __syncthreads();
    if (ty == 0) {
        atomicAdd(&g_stats[f], ss[0][f] + ss[1][f] + ss[2][f] + ss[3][f]);
        atomicAdd(&g_stats[64 + f], ss2[0][f] + ss2[1][f] + ss2[2][f] + ss2[3][f]);
    }
}

// ---------------- fold BN into W2/b2 (1 block, 64 threads) ----------------
__global__ void bn_finalize(const float* __restrict__ gam, const float* __restrict__ be,
                            const float* __restrict__ W2, const float* __restrict__ b2) {
    int j = threadIdx.x;
    __shared__ float scale[64], shift[64];
    const float inv_n = 1.0f / (float)NN;
    float mu = g_stats[j] * inv_n;
    float var = g_stats[64 + j] * inv_n - mu * mu;
    float sc = gam[j] * rsqrtf(var + 1e-5f);
    scale[j] = sc;
    shift[j] = be[j] - mu * sc;
    __syncthreads();
    float acc = b2[j];
#pragma unroll 8
    for (int k = 0; k < 64; k++) {
        float w = W2[k * 64 + j];
        g_W2p[k * 64 + j] = scale[k] * w;
        acc += shift[k] * w;
    }
    g_b2p[j] = acc;
}

// ---------------- global add pooling ----------------
__global__ __launch_bounds__(256) void pool_kernel(const float* __restrict__ h,
                                                   const int* __restrict__ batch,
                                                   float* __restrict__ xg) {
    long long idx = (long long)blockIdx.x * 256 + threadIdx.x;  // over NN*16
    int i = (int)(idx >> 4);
    if (i >= NN) return;
    int c = ((int)idx & 15) * 4;
    int b = __ldg(batch + i);
    float4 v = *(const float4*)(h + (size_t)i * 64 + c);
    float* a = xg + (size_t)b * 64 + c;
    atomicAdd(a + 0, v.x);
    atomicAdd(a + 1, v.y);
    atomicAdd(a + 2, v.z);
    atomicAdd(a + 3, v.w);
}

extern "C" void kernel_launch(void* const* d_in, const int* in_sizes, int n_in,
                              void* d_out, int out_size) {
    const float* x     = (const float*)d_in[0];
    const int*   ei    = (const int*)d_in[1];
    const int*   batch = (const int*)d_in[2];
    const float* W1_0  = (const float*)d_in[3];
    const float* b1_0  = (const float*)d_in[4];
    const float* g_0   = (const float*)d_in[5];
    const float* be_0  = (const float*)d_in[6];
    const float* W2_0  = (const float*)d_in[7];
    const float* b2_0  = (const float*)d_in[8];
    const float* W1_1  = (const float*)d_in[9];
    const float* b1_1  = (const float*)d_in[10];
    const float* g_1   = (const float*)d_in[11];
    const float* be_1  = (const float*)d_in[12];
    const float* W2_1  = (const float*)d_in[13];
    const float* b2_1  = (const float*)d_in[14];

    const int* src = ei;
    const int* dst = ei + EE;

    float *z, *agg, *h, *stats, *W2p, *b2p;
    cudaGetSymbolAddress((void**)&z, g_z);
    cudaGetSymbolAddress((void**)&agg, g_agg);
    cudaGetSymbolAddress((void**)&h, g_h);
    cudaGetSymbolAddress((void**)&stats, g_stats);
    cudaGetSymbolAddress((void**)&W2p, g_W2p);
    cudaGetSymbolAddress((void**)&b2p, g_b2p);

    float* out  = (float*)d_out;
    float* xg   = out;            // first: (G, 64)
    float* hout = out + GG * 64;  // then:  (N, 64)

    const int gemm_blocks = (NN + 63) / 64;
    const int edge_blocks = (int)(((long long)EE * 16 + 255) / 256);
    const int pool_blocks = (int)(((long long)NN * 16 + 255) / 256);

    // ---------- layer 0 ----------
    cudaMemsetAsync(agg, 0, (size_t)NN * 64 * sizeof(float));
    cudaMemsetAsync(stats, 0, 128 * sizeof(float));
    gemm64<128, false, false><<<gemm_blocks, 256>>>(x, W1_0, nullptr, z, NN);
    edge_agg<<<edge_blocks, 256>>>(src, dst, z, agg);
    postagg<<<512, 256>>>(z, agg, b1_0, NN);
    bn_finalize<<<1, 64>>>(g_0, be_0, W2_0, b2_0);
    gemm64<64, true, true><<<gemm_blocks, 256>>>(z, W2p, b2p, h, NN);

    // ---------- layer 1 ----------
    cudaMemsetAsync(agg, 0, (size_t)NN * 64 * sizeof(float));
    cudaMemsetAsync(stats, 0, 128 * sizeof(float));
    gemm64<64, false, false><<<gemm_blocks, 256>>>(h, W1_1, nullptr, z, NN);
    edge_agg<<<edge_blocks, 256>>>(src, dst, z, agg);
    postagg<<<512, 256>>>(z, agg, b1_1, NN);
    bn_finalize<<<1, 64>>>(g_1, be_1, W2_1, b2_1);
    gemm64<64, true, true><<<gemm_blocks, 256>>>(z, W2p, b2p, hout, NN);

    // ---------- pooling ----------
    cudaMemsetAsync(xg, 0, (size_t)GG * 64 * sizeof(float));
    pool_kernel<<<pool_blocks, 256>>>(hout, batch, xg);
}

// round 2
// speedup vs baseline: 1.9295x; 1.9295x over previous
#include <cuda_runtime.h>
#include <math.h>

#define NN 100000
#define EE 3200000
#define GG 1024

// ---------------- scratch (no allocations allowed) ----------------
__device__ float g_z[NN * 64];       // z = X @ W1 (then u = relu(z+agg+b1) in place)
__device__ float g_agg[NN * 64];     // edge aggregation accumulator
__device__ float g_h[NN * 64];       // z' buffer for layer 1
__device__ float g_stats[128];       // [0:64) sum, [64:128) sumsq
__device__ float g_W2p[64 * 64];     // BN-folded W2
__device__ float g_b2p[64];          // BN-folded b2

__device__ __forceinline__ void red_add_v4(float* addr, float4 v) {
    asm volatile("red.global.add.v4.f32 [%0], {%1, %2, %3, %4};"
                 :: "l"(addr), "f"(v.x), "f"(v.y), "f"(v.z), "f"(v.w)
                 : "memory");
}

// ---------------- GEMM: out[n,64] = X[n,K] @ W[K,64] (+bias, +relu, +pool) ----------------
template <int K, bool RELU, bool BIAS, bool POOL>
__global__ __launch_bounds__(256) void gemm64(const float* __restrict__ X,
                                              const float* __restrict__ W,
                                              const float* __restrict__ bias,
                                              float* __restrict__ out, int n,
                                              const int* __restrict__ batch,
                                              float* __restrict__ xg) {
    __shared__ float Xs[64][68];   // padded (68*4=272B row, 16B-aligned cols)
    __shared__ float Ws[64][64];
    const int tid  = threadIdx.x;
    const int row0 = blockIdx.x * 64;
    const int col4 = (tid & 15) * 4;
    const int row4 = (tid >> 4) * 4;

    float acc[4][4];
#pragma unroll
    for (int r = 0; r < 4; r++)
#pragma unroll
        for (int c = 0; c < 4; c++) acc[r][c] = 0.f;

    for (int k0 = 0; k0 < K; k0 += 64) {
#pragma unroll
        for (int t = 0; t < 4; t++) {
            int fidx = t * 256 + tid;
            int r = fidx >> 4;
            int c = (fidx & 15) * 4;
            float4 v = make_float4(0.f, 0.f, 0.f, 0.f);
            int row = row0 + r;
            if (row < n) v = *(const float4*)(X + (size_t)row * K + k0 + c);
            *(float4*)&Xs[r][c] = v;
        }
#pragma unroll
        for (int t = 0; t < 4; t++) {
            int fidx = t * 256 + tid;
            int kk = fidx >> 4;
            int c = (fidx & 15) * 4;
            *(float4*)&Ws[kk][c] = *(const float4*)(W + (size_t)(k0 + kk) * 64 + c);
        }
        __syncthreads();
#pragma unroll
        for (int kk = 0; kk < 64; kk += 4) {
            float4 wv0 = *(float4*)&Ws[kk + 0][col4];
            float4 wv1 = *(float4*)&Ws[kk + 1][col4];
            float4 wv2 = *(float4*)&Ws[kk + 2][col4];
            float4 wv3 = *(float4*)&Ws[kk + 3][col4];
#pragma unroll
            for (int r = 0; r < 4; r++) {
                float4 xv = *(float4*)&Xs[row4 + r][kk];
                acc[r][0] += xv.x * wv0.x + xv.y * wv1.x + xv.z * wv2.x + xv.w * wv3.x;
                acc[r][1] += xv.x * wv0.y + xv.y * wv1.y + xv.z * wv2.y + xv.w * wv3.y;
                acc[r][2] += xv.x * wv0.z + xv.y * wv1.z + xv.z * wv2.z + xv.w * wv3.z;
                acc[r][3] += xv.x * wv0.w + xv.y * wv1.w + xv.z * wv2.w + xv.w * wv3.w;
            }
        }
        __syncthreads();
    }
#pragma unroll
    for (int r = 0; r < 4; r++) {
        int row = row0 + row4 + r;
        if (row < n) {
            float4 o = make_float4(acc[r][0], acc[r][1], acc[r][2], acc[r][3]);
            if (BIAS) {
                o.x += bias[col4 + 0]; o.y += bias[col4 + 1];
                o.z += bias[col4 + 2]; o.w += bias[col4 + 3];
            }
            if (RELU) {
                o.x = fmaxf(o.x, 0.f); o.y = fmaxf(o.y, 0.f);
                o.z = fmaxf(o.z, 0.f); o.w = fmaxf(o.w, 0.f);
            }
            *(float4*)(out + (size_t)row * 64 + col4) = o;
            if (POOL) {
                int b = __ldg(batch + row);
                red_add_v4(xg + (size_t)b * 64 + col4, o);
            }
        }
    }
}

// --------- fused middle: z' = relu(U @ W2p + b2p) @ W1_1, no h round-trip ---------
__global__ __launch_bounds__(256) void gemm_mid(const float* __restrict__ U,
                                                const float* __restrict__ W2p,
                                                const float* __restrict__ b2p,
                                                const float* __restrict__ W1_1,
                                                float* __restrict__ out, int n) {
    __shared__ float Xs[64][68];
    __shared__ float Ws[64][64];
    const int tid  = threadIdx.x;
    const int row0 = blockIdx.x * 64;
    const int col4 = (tid & 15) * 4;
    const int row4 = (tid >> 4) * 4;

    float acc[4][4];
#pragma unroll
    for (int r = 0; r < 4; r++)
#pragma unroll
        for (int c = 0; c < 4; c++) acc[r][c] = 0.f;

    // stage U tile + W2p
#pragma unroll
    for (int t = 0; t < 4; t++) {
        int fidx = t * 256 + tid;
        int r = fidx >> 4;
        int c = (fidx & 15) * 4;
        float4 v = make_float4(0.f, 0.f, 0.f, 0.f);
        int row = row0 + r;
        if (row < n) v = *(const float4*)(U + (size_t)row * 64 + c);
        *(float4*)&Xs[r][c] = v;
        *(float4*)&Ws[r][c] = *(const float4*)(W2p + (size_t)r * 64 + c);
    }
    __syncthreads();
#pragma unroll
    for (int kk = 0; kk < 64; kk += 4) {
        float4 wv0 = *(float4*)&Ws[kk + 0][col4];
        float4 wv1 = *(float4*)&Ws[kk + 1][col4];
        float4 wv2 = *(float4*)&Ws[kk + 2][col4];
        float4 wv3 = *(float4*)&Ws[kk + 3][col4];
#pragma unroll
        for (int r = 0; r < 4; r++) {
            float4 xv = *(float4*)&Xs[row4 + r][kk];
            acc[r][0] += xv.x * wv0.x + xv.y * wv1.x + xv.z * wv2.x + xv.w * wv3.x;
            acc[r][1] += xv.x * wv0.y + xv.y * wv1.y + xv.z * wv2.y + xv.w * wv3.y;
            acc[r][2] += xv.x * wv0.z + xv.y * wv1.z + xv.z * wv2.z + xv.w * wv3.z;
            acc[r][3] += xv.x * wv0.w + xv.y * wv1.w + xv.z * wv2.w + xv.w * wv3.w;
        }
    }
    __syncthreads();  // all reads of Xs done; safe to overwrite

    // h = relu(acc + b2p) -> back into Xs; stage W1_1
    float4 bb = *(const float4*)(b2p + col4);
#pragma unroll
    for (int r = 0; r < 4; r++) {
        float4 h;
        h.x = fmaxf(acc[r][0] + bb.x, 0.f);
        h.y = fmaxf(acc[r][1] + bb.y, 0.f);
        h.z = fmaxf(acc[r][2] + bb.z, 0.f);
        h.w = fmaxf(acc[r][3] + bb.w, 0.f);
        *(float4*)&Xs[row4 + r][col4] = h;
        acc[r][0] = acc[r][1] = acc[r][2] = acc[r][3] = 0.f;
    }
#pragma unroll
    for (int t = 0; t < 4; t++) {
        int fidx = t * 256 + tid;
        int kk = fidx >> 4;
        int c = (fidx & 15) * 4;
        *(float4*)&Ws[kk][c] = *(const float4*)(W1_1 + (size_t)kk * 64 + c);
    }
    __syncthreads();
#pragma unroll
    for (int kk = 0; kk < 64; kk += 4) {
        float4 wv0 = *(float4*)&Ws[kk + 0][col4];
        float4 wv1 = *(float4*)&Ws[kk + 1][col4];
        float4 wv2 = *(float4*)&Ws[kk + 2][col4];
        float4 wv3 = *(float4*)&Ws[kk + 3][col4];
#pragma unroll
        for (int r = 0; r < 4; r++) {
            float4 xv = *(float4*)&Xs[row4 + r][kk];
            acc[r][0] += xv.x * wv0.x + xv.y * wv1.x + xv.z * wv2.x + xv.w * wv3.x;
            acc[r][1] += xv.x * wv0.y + xv.y * wv1.y + xv.z * wv2.y + xv.w * wv3.y;
            acc[r][2] += xv.x * wv0.z + xv.y * wv1.z + xv.z * wv2.z + xv.w * wv3.z;
            acc[r][3] += xv.x * wv0.w + xv.y * wv1.w + xv.z * wv2.w + xv.w * wv3.w;
        }
    }
#pragma unroll
    for (int r = 0; r < 4; r++) {
        int row = row0 + row4 + r;
        if (row < n)
            *(float4*)(out + (size_t)row * 64 + col4) =
                make_float4(acc[r][0], acc[r][1], acc[r][2], acc[r][3]);
    }
}

// ---------------- edge scatter-add: agg[dst] += z[src], vector reductions ----------------
__global__ __launch_bounds__(256) void edge_agg(const int* __restrict__ src,
                                                const int* __restrict__ dst,
                                                const float* __restrict__ z,
                                                float* __restrict__ agg) {
    long long idx = (long long)blockIdx.x * 256 + threadIdx.x;  // over EE*16
    int e = (int)(idx >> 4);
    if (e >= EE) return;
    int c = ((int)idx & 15) * 4;
    int s = __ldg(src + e);
    int d = __ldg(dst + e);
    float4 v = __ldg((const float4*)(z + (size_t)s * 64 + c));
    red_add_v4(agg + (size_t)d * 64 + c, v);
}

// ---------------- fused: u = relu(z + agg + b1); channel sum/sumsq ----------------
__global__ __launch_bounds__(256) void postagg(float* __restrict__ z,
                                               const float* __restrict__ agg,
                                               const float* __restrict__ b1, int n) {
    const int f = threadIdx.x & 63;
    const int ty = threadIdx.x >> 6;
    const float b = b1[f];
    float s = 0.f, s2 = 0.f;
    for (int i = blockIdx.x * 4 + ty; i < n; i += gridDim.x * 4) {
        size_t o = (size_t)i * 64 + f;
        float u = fmaxf(z[o] + agg[o] + b, 0.f);
        z[o] = u;
        s += u;
        s2 += u * u;
    }
    __shared__ float ss[4][64], ss2[4][64];
    ss[ty][f] = s;
    ss2[ty][f] = s2;
    __syncthreads();
    if (ty == 0) {
        atomicAdd(&g_stats[f], ss[0][f] + ss[1][f] + ss[2][f] + ss[3][f]);
        atomicAdd(&g_stats[64 + f], ss2[0][f] + ss2[1][f] + ss2[2][f] + ss2[3][f]);
    }
}

// ---------------- fold BN into W2/b2 (1 block, 256 threads) ----------------
__global__ void bn_finalize(const float* __restrict__ gam, const float* __restrict__ be,
                            const float* __restrict__ W2, const float* __restrict__ b2) {
    const int j = threadIdx.x & 63;
    const int q = threadIdx.x >> 6;  // 0..3
    __shared__ float scale[64], shift[64];
    __shared__ float pa[4][64];
    if (q == 0) {
        const float inv_n = 1.0f / (float)NN;
        float mu = g_stats[j] * inv_n;
        float var = g_stats[64 + j] * inv_n - mu * mu;
        float sc = gam[j] * rsqrtf(var + 1e-5f);
        scale[j] = sc;
        shift[j] = be[j] - mu * sc;
    }
    __syncthreads();
    float acc = 0.f;
#pragma unroll
    for (int t = 0; t < 16; t++) {
        int k = q * 16 + t;
        float w = W2[k * 64 + j];
        g_W2p[k * 64 + j] = scale[k] * w;
        acc += shift[k] * w;
    }
    pa[q][j] = acc;
    __syncthreads();
    if (q == 0) g_b2p[j] = b2[j] + pa[0][j] + pa[1][j] + pa[2][j] + pa[3][j];
}

extern "C" void kernel_launch(void* const* d_in, const int* in_sizes, int n_in,
                              void* d_out, int out_size) {
    const float* x     = (const float*)d_in[0];
    const int*   ei    = (const int*)d_in[1];
    const int*   batch = (const int*)d_in[2];
    const float* W1_0  = (const float*)d_in[3];
    const float* b1_0  = (const float*)d_in[4];
    const float* g_0   = (const float*)d_in[5];
    const float* be_0  = (const float*)d_in[6];
    const float* W2_0  = (const float*)d_in[7];
    const float* b2_0  = (const float*)d_in[8];
    const float* W1_1  = (const float*)d_in[9];
    const float* b1_1  = (const float*)d_in[10];
    const float* g_1   = (const float*)d_in[11];
    const float* be_1  = (const float*)d_in[12];
    const float* W2_1  = (const float*)d_in[13];
    const float* b2_1  = (const float*)d_in[14];

    const int* src = ei;
    const int* dst = ei + EE;

    float *z, *agg, *z2, *stats, *W2p, *b2p;
    cudaGetSymbolAddress((void**)&z, g_z);
    cudaGetSymbolAddress((void**)&agg, g_agg);
    cudaGetSymbolAddress((void**)&z2, g_h);
    cudaGetSymbolAddress((void**)&stats, g_stats);
    cudaGetSymbolAddress((void**)&W2p, g_W2p);
    cudaGetSymbolAddress((void**)&b2p, g_b2p);

    float* out  = (float*)d_out;
    float* xg   = out;            // (G, 64)
    float* hout = out + GG * 64;  // (N, 64)

    const int gemm_blocks = (NN + 63) / 64;
    const int edge_blocks = (int)(((long long)EE * 16 + 255) / 256);

    // ---------- layer 0 ----------
    cudaMemsetAsync(agg, 0, (size_t)NN * 64 * sizeof(float));
    cudaMemsetAsync(stats, 0, 128 * sizeof(float));
    cudaMemsetAsync(xg, 0, (size_t)GG * 64 * sizeof(float));
    gemm64<128, false, false, false><<<gemm_blocks, 256>>>(x, W1_0, nullptr, z, NN, nullptr, nullptr);
    edge_agg<<<edge_blocks, 256>>>(src, dst, z, agg);
    postagg<<<512, 256>>>(z, agg, b1_0, NN);
    bn_finalize<<<1, 256>>>(g_0, be_0, W2_0, b2_0);
    gemm_mid<<<gemm_blocks, 256>>>(z, W2p, b2p, W1_1, z2, NN);

    // ---------- layer 1 ----------
    cudaMemsetAsync(agg, 0, (size_t)NN * 64 * sizeof(float));
    cudaMemsetAsync(stats, 0, 128 * sizeof(float));
    edge_agg<<<edge_blocks, 256>>>(src, dst, z2, agg);
    postagg<<<512, 256>>>(z2, agg, b1_1, NN);
    bn_finalize<<<1, 256>>>(g_1, be_1, W2_1, b2_1);
    gemm64<64, true, true, true><<<gemm_blocks, 256>>>(z2, W2p, b2p, hout, NN, batch, xg);
}

// round 4
// speedup vs baseline: 2.2051x; 1.1428x over previous
#include <cuda_runtime.h>
#include <math.h>

#define NN 100000
#define EE 3200000
#define GG 1024
#define NREP 64   // stats replicas

// ---------------- scratch (no allocations allowed) ----------------
__device__ float g_z[NN * 64];        // zA (layer0 pre-act), later u2
__device__ float g_u[NN * 64];        // uA = relu(z+agg+b1) layer 0
__device__ float g_h[NN * 64];        // z2 (layer1 pre-act)
__device__ float g_statsP[NREP * 128]; // replicated [sum(64), sumsq(64)]
__device__ float g_W2p[64 * 64];
__device__ float g_b2p[64];
__device__ int   g_cur[NN];           // degree, then scatter cursor
__device__ int   g_off[NN + 1];       // CSR offsets
__device__ int   g_col[EE];           // CSR column (src) list

__device__ __forceinline__ void red_add_v4(float* addr, float4 v) {
    asm volatile("red.global.add.v4.f32 [%0], {%1, %2, %3, %4};"
                 :: "l"(addr), "f"(v.x), "f"(v.y), "f"(v.z), "f"(v.w)
                 : "memory");
}
__device__ __forceinline__ void red_add_f(float* addr, float v) {
    asm volatile("red.global.add.f32 [%0], %1;" :: "l"(addr), "f"(v) : "memory");
}

// ================= CSR build =================
__global__ __launch_bounds__(256) void hist_kernel(const int* __restrict__ dst) {
    int e = blockIdx.x * 256 + threadIdx.x;
    if (e < EE) atomicAdd(&g_cur[__ldg(dst + e)], 1);
}

__global__ __launch_bounds__(1024) void scan_kernel() {
    __shared__ int part[1024];
    const int C = (NN + 1023) / 1024;   // 98
    const int t = threadIdx.x;
    const int begin = t * C;
    const int end = min(begin + C, NN);
    int s = 0;
    for (int i = begin; i < end; i++) s += g_cur[i];
    part[t] = s;
    __syncthreads();
    for (int d = 1; d < 1024; d <<= 1) {
        int v = (t >= d) ? part[t - d] : 0;
        __syncthreads();
        part[t] += v;
        __syncthreads();
    }
    int run = (t == 0) ? 0 : part[t - 1];
    for (int i = begin; i < end; i++) {
        int d = g_cur[i];
        g_off[i] = run;
        g_cur[i] = run;   // cursor for scatter
        run += d;
    }
    if (t == 1023) g_off[NN] = run;
}

__global__ __launch_bounds__(256) void scatter_kernel(const int* __restrict__ src,
                                                      const int* __restrict__ dst) {
    int e = blockIdx.x * 256 + threadIdx.x;
    if (e < EE) {
        int pos = atomicAdd(&g_cur[__ldg(dst + e)], 1);
        g_col[pos] = __ldg(src + e);
    }
}

// ========== fused gather + self + bias + relu + stats ==========
// one warp per node; 8 nodes per 256-thread block
__global__ __launch_bounds__(256) void gather_post(const float* __restrict__ z,
                                                   const float* __restrict__ b1,
                                                   float* __restrict__ u) {
    __shared__ float ssum[8][64];
    __shared__ float ssq[8][64];
    const int warp = threadIdx.x >> 5;
    const int lane = threadIdx.x & 31;
    const int n = blockIdx.x * 8 + warp;
    const int half = lane >> 4;           // 0 or 1
    const int c4 = (lane & 15) * 4;       // feature offset

    const int beg = __ldg(&g_off[n]);
    const int endo = __ldg(&g_off[n + 1]);

    float4 acc = make_float4(0.f, 0.f, 0.f, 0.f);
    int j = beg + half;
    // unroll-by-2 per half (4 edges in flight per warp)
    for (; j + 2 < endo; j += 4) {
        int s0 = __ldg(&g_col[j]);
        int s1 = __ldg(&g_col[j + 2]);
        float4 v0 = __ldg((const float4*)(z + (size_t)s0 * 64 + c4));
        float4 v1 = __ldg((const float4*)(z + (size_t)s1 * 64 + c4));
        acc.x += v0.x + v1.x; acc.y += v0.y + v1.y;
        acc.z += v0.z + v1.z; acc.w += v0.w + v1.w;
    }
    if (j < endo) {
        int s0 = __ldg(&g_col[j]);
        float4 v0 = __ldg((const float4*)(z + (size_t)s0 * 64 + c4));
        acc.x += v0.x; acc.y += v0.y; acc.z += v0.z; acc.w += v0.w;
    }
    // combine the two halves
    acc.x += __shfl_down_sync(0xffffffffu, acc.x, 16);
    acc.y += __shfl_down_sync(0xffffffffu, acc.y, 16);
    acc.z += __shfl_down_sync(0xffffffffu, acc.z, 16);
    acc.w += __shfl_down_sync(0xffffffffu, acc.w, 16);

    if (half == 0) {
        float4 zz = __ldg((const float4*)(z + (size_t)n * 64 + c4));
        float4 bb = __ldg((const float4*)(b1 + c4));
        float4 o;
        o.x = fmaxf(zz.x + acc.x + bb.x, 0.f);
        o.y = fmaxf(zz.y + acc.y + bb.y, 0.f);
        o.z = fmaxf(zz.z + acc.z + bb.z, 0.f);
        o.w = fmaxf(zz.w + acc.w + bb.w, 0.f);
        *(float4*)(u + (size_t)n * 64 + c4) = o;
        *(float4*)&ssum[warp][c4] = o;
        float4 q = make_float4(o.x * o.x, o.y * o.y, o.z * o.z, o.w * o.w);
        *(float4*)&ssq[warp][c4] = q;
    }
    __syncthreads();
    // block-reduce 8 warps -> per-feature, then replicated global red
    const int tid = threadIdx.x;
    const int rep = blockIdx.x & (NREP - 1);
    if (tid < 64) {
        float s = 0.f;
#pragma unroll
        for (int w = 0; w < 8; w++) s += ssum[w][tid];
        red_add_f(&g_statsP[rep * 128 + tid], s);
    } else if (tid < 128) {
        int f = tid - 64;
        float s = 0.f;
#pragma unroll
        for (int w = 0; w < 8; w++) s += ssq[w][f];
        red_add_f(&g_statsP[rep * 128 + 64 + f], s);
    }
}

// ---------------- GEMM: out[n,64] = X[n,K] @ W[K,64] (+bias, +relu, +pool) ----------------
template <int K, bool RELU, bool BIAS, bool POOL>
__global__ __launch_bounds__(256) void gemm64(const float* __restrict__ X,
                                              const float* __restrict__ W,
                                              const float* __restrict__ bias,
                                              float* __restrict__ out, int n,
                                              const int* __restrict__ batch,
                                              float* __restrict__ xg) {
    __shared__ float Xs[64][68];
    __shared__ float Ws[64][64];
    const int tid  = threadIdx.x;
    const int row0 = blockIdx.x * 64;
    const int col4 = (tid & 15) * 4;
    const int row4 = (tid >> 4) * 4;

    float acc[4][4];
#pragma unroll
    for (int r = 0; r < 4; r++)
#pragma unroll
        for (int c = 0; c < 4; c++) acc[r][c] = 0.f;

    for (int k0 = 0; k0 < K; k0 += 64) {
#pragma unroll
        for (int t = 0; t < 4; t++) {
            int fidx = t * 256 + tid;
            int r = fidx >> 4;
            int c = (fidx & 15) * 4;
            float4 v = make_float4(0.f, 0.f, 0.f, 0.f);
            int row = row0 + r;
            if (row < n) v = *(const float4*)(X + (size_t)row * K + k0 + c);
            *(float4*)&Xs[r][c] = v;
        }
#pragma unroll
        for (int t = 0; t < 4; t++) {
            int fidx = t * 256 + tid;
            int kk = fidx >> 4;
            int c = (fidx & 15) * 4;
            *(float4*)&Ws[kk][c] = *(const float4*)(W + (size_t)(k0 + kk) * 64 + c);
        }
        __syncthreads();
#pragma unroll
        for (int kk = 0; kk < 64; kk += 4) {
            float4 wv0 = *(float4*)&Ws[kk + 0][col4];
            float4 wv1 = *(float4*)&Ws[kk + 1][col4];
            float4 wv2 = *(float4*)&Ws[kk + 2][col4];
            float4 wv3 = *(float4*)&Ws[kk + 3][col4];
#pragma unroll
            for (int r = 0; r < 4; r++) {
                float4 xv = *(float4*)&Xs[row4 + r][kk];
                acc[r][0] += xv.x * wv0.x + xv.y * wv1.x + xv.z * wv2.x + xv.w * wv3.x;
                acc[r][1] += xv.x * wv0.y + xv.y * wv1.y + xv.z * wv2.y + xv.w * wv3.y;
                acc[r][2] += xv.x * wv0.z + xv.y * wv1.z + xv.z * wv2.z + xv.w * wv3.z;
                acc[r][3] += xv.x * wv0.w + xv.y * wv1.w + xv.z * wv2.w + xv.w * wv3.w;
            }
        }
        __syncthreads();
    }
#pragma unroll
    for (int r = 0; r < 4; r++) {
        int row = row0 + row4 + r;
        if (row < n) {
            float4 o = make_float4(acc[r][0], acc[r][1], acc[r][2], acc[r][3]);
            if (BIAS) {
                o.x += bias[col4 + 0]; o.y += bias[col4 + 1];
                o.z += bias[col4 + 2]; o.w += bias[col4 + 3];
            }
            if (RELU) {
                o.x = fmaxf(o.x, 0.f); o.y = fmaxf(o.y, 0.f);
                o.z = fmaxf(o.z, 0.f); o.w = fmaxf(o.w, 0.f);
            }
            *(float4*)(out + (size_t)row * 64 + col4) = o;
            if (POOL) {
                int b = __ldg(batch + row);
                red_add_v4(xg + (size_t)b * 64 + col4, o);
            }
        }
    }
}

// --------- fused middle: z' = relu(U @ W2p + b2p) @ W1_1 ---------
__global__ __launch_bounds__(256) void gemm_mid(const float* __restrict__ U,
                                                const float* __restrict__ W2p,
                                                const float* __restrict__ b2p,
                                                const float* __restrict__ W1_1,
                                                float* __restrict__ out, int n) {
    __shared__ float Xs[64][68];
    __shared__ float Ws[64][64];
    const int tid  = threadIdx.x;
    const int row0 = blockIdx.x * 64;
    const int col4 = (tid & 15) * 4;
    const int row4 = (tid >> 4) * 4;

    float acc[4][4];
#pragma unroll
    for (int r = 0; r < 4; r++)
#pragma unroll
        for (int c = 0; c < 4; c++) acc[r][c] = 0.f;

#pragma unroll
    for (int t = 0; t < 4; t++) {
        int fidx = t * 256 + tid;
        int r = fidx >> 4;
        int c = (fidx & 15) * 4;
        float4 v = make_float4(0.f, 0.f, 0.f, 0.f);
        int row = row0 + r;
        if (row < n) v = *(const float4*)(U + (size_t)row * 64 + c);
        *(float4*)&Xs[r][c] = v;
        *(float4*)&Ws[r][c] = *(const float4*)(W2p + (size_t)r * 64 + c);
    }
    __syncthreads();
#pragma unroll
    for (int kk = 0; kk < 64; kk += 4) {
        float4 wv0 = *(float4*)&Ws[kk + 0][col4];
        float4 wv1 = *(float4*)&Ws[kk + 1][col4];
        float4 wv2 = *(float4*)&Ws[kk + 2][col4];
        float4 wv3 = *(float4*)&Ws[kk + 3][col4];
#pragma unroll
        for (int r = 0; r < 4; r++) {
            float4 xv = *(float4*)&Xs[row4 + r][kk];
            acc[r][0] += xv.x * wv0.x + xv.y * wv1.x + xv.z * wv2.x + xv.w * wv3.x;
            acc[r][1] += xv.x * wv0.y + xv.y * wv1.y + xv.z * wv2.y + xv.w * wv3.y;
            acc[r][2] += xv.x * wv0.z + xv.y * wv1.z + xv.z * wv2.z + xv.w * wv3.z;
            acc[r][3] += xv.x * wv0.w + xv.y * wv1.w + xv.z * wv2.w + xv.w * wv3.w;
        }
    }
    __syncthreads();

    float4 bb = *(const float4*)(b2p + col4);
#pragma unroll
    for (int r = 0; r < 4; r++) {
        float4 h;
        h.x = fmaxf(acc[r][0] + bb.x, 0.f);
        h.y = fmaxf(acc[r][1] + bb.y, 0.f);
        h.z = fmaxf(acc[r][2] + bb.z, 0.f);
        h.w = fmaxf(acc[r][3] + bb.w, 0.f);
        *(float4*)&Xs[row4 + r][col4] = h;
        acc[r][0] = acc[r][1] = acc[r][2] = acc[r][3] = 0.f;
    }
#pragma unroll
    for (int t = 0; t < 4; t++) {
        int fidx = t * 256 + tid;
        int kk = fidx >> 4;
        int c = (fidx & 15) * 4;
        *(float4*)&Ws[kk][c] = *(const float4*)(W1_1 + (size_t)kk * 64 + c);
    }
    __syncthreads();
#pragma unroll
    for (int kk = 0; kk < 64; kk += 4) {
        float4 wv0 = *(float4*)&Ws[kk + 0][col4];
        float4 wv1 = *(float4*)&Ws[kk + 1][col4];
        float4 wv2 = *(float4*)&Ws[kk + 2][col4];
        float4 wv3 = *(float4*)&Ws[kk + 3][col4];
#pragma unroll
        for (int r = 0; r < 4; r++) {
            float4 xv = *(float4*)&Xs[row4 + r][kk];
            acc[r][0] += xv.x * wv0.x + xv.y * wv1.x + xv.z * wv2.x + xv.w * wv3.x;
            acc[r][1] += xv.x * wv0.y + xv.y * wv1.y + xv.z * wv2.y + xv.w * wv3.y;
            acc[r][2] += xv.x * wv0.z + xv.y * wv1.z + xv.z * wv2.z + xv.w * wv3.z;
            acc[r][3] += xv.x * wv0.w + xv.y * wv1.w + xv.z * wv2.w + xv.w * wv3.w;
        }
    }
#pragma unroll
    for (int r = 0; r < 4; r++) {
        int row = row0 + row4 + r;
        if (row < n)
            *(float4*)(out + (size_t)row * 64 + col4) =
                make_float4(acc[r][0], acc[r][1], acc[r][2], acc[r][3]);
    }
}

// ---------------- fold BN into W2/b2 ----------------
__global__ void bn_finalize(const float* __restrict__ gam, const float* __restrict__ be,
                            const float* __restrict__ W2, const float* __restrict__ b2) {
    const int j = threadIdx.x & 63;
    const int q = threadIdx.x >> 6;  // 0..3
    __shared__ float scale[64], shift[64];
    __shared__ float pa[4][64];
    if (q == 0) {
        float sum = 0.f, sq = 0.f;
#pragma unroll 8
        for (int r = 0; r < NREP; r++) {
            sum += g_statsP[r * 128 + j];
            sq  += g_statsP[r * 128 + 64 + j];
        }
        const float inv_n = 1.0f / (float)NN;
        float mu = sum * inv_n;
        float var = sq * inv_n - mu * mu;
        float sc = gam[j] * rsqrtf(var + 1e-5f);
        scale[j] = sc;
        shift[j] = be[j] - mu * sc;
    }
    __syncthreads();
    float acc = 0.f;
#pragma unroll
    for (int t = 0; t < 16; t++) {
        int k = q * 16 + t;
        float w = W2[k * 64 + j];
        g_W2p[k * 64 + j] = scale[k] * w;
        acc += shift[k] * w;
    }
    pa[q][j] = acc;
    __syncthreads();
    if (q == 0) g_b2p[j] = b2[j] + pa[0][j] + pa[1][j] + pa[2][j] + pa[3][j];
}

extern "C" void kernel_launch(void* const* d_in, const int* in_sizes, int n_in,
                              void* d_out, int out_size) {
    const float* x     = (const float*)d_in[0];
    const int*   ei    = (const int*)d_in[1];
    const int*   batch = (const int*)d_in[2];
    const float* W1_0  = (const float*)d_in[3];
    const float* b1_0  = (const float*)d_in[4];
    const float* g_0   = (const float*)d_in[5];
    const float* be_0  = (const float*)d_in[6];
    const float* W2_0  = (const float*)d_in[7];
    const float* b2_0  = (const float*)d_in[8];
    const float* W1_1  = (const float*)d_in[9];
    const float* b1_1  = (const float*)d_in[10];
    const float* g_1   = (const float*)d_in[11];
    const float* be_1  = (const float*)d_in[12];
    const float* W2_1  = (const float*)d_in[13];
    const float* b2_1  = (const float*)d_in[14];

    const int* src = ei;
    const int* dst = ei + EE;

    float *zA, *uA, *z2, *statsP, *W2p, *b2p;
    int *cur;
    cudaGetSymbolAddress((void**)&zA, g_z);
    cudaGetSymbolAddress((void**)&uA, g_u);
    cudaGetSymbolAddress((void**)&z2, g_h);
    cudaGetSymbolAddress((void**)&statsP, g_statsP);
    cudaGetSymbolAddress((void**)&W2p, g_W2p);
    cudaGetSymbolAddress((void**)&b2p, g_b2p);
    cudaGetSymbolAddress((void**)&cur, g_cur);

    float* out  = (float*)d_out;
    float* xg   = out;            // (G, 64)
    float* hout = out + GG * 64;  // (N, 64)

    const int gemm_blocks = (NN + 63) / 64;
    const int edge_blocks = (EE + 255) / 256;
    const int node_blocks = NN / 8;   // 12500, exact

    // ---------- CSR build (once, reused by both layers) ----------
    cudaMemsetAsync(cur, 0, NN * sizeof(int));
    hist_kernel<<<edge_blocks, 256>>>(dst);
    scan_kernel<<<1, 1024>>>();
    scatter_kernel<<<edge_blocks, 256>>>(src, dst);

    // ---------- layer 0 ----------
    cudaMemsetAsync(statsP, 0, NREP * 128 * sizeof(float));
    cudaMemsetAsync(xg, 0, (size_t)GG * 64 * sizeof(float));
    gemm64<128, false, false, false><<<gemm_blocks, 256>>>(x, W1_0, nullptr, zA, NN, nullptr, nullptr);
    gather_post<<<node_blocks, 256>>>(zA, b1_0, uA);
    bn_finalize<<<1, 256>>>(g_0, be_0, W2_0, b2_0);
    gemm_mid<<<gemm_blocks, 256>>>(uA, W2p, b2p, W1_1, z2, NN);

    // ---------- layer 1 ----------
    cudaMemsetAsync(statsP, 0, NREP * 128 * sizeof(float));
    gather_post<<<node_blocks, 256>>>(z2, b1_1, zA);   // u2 -> zA buffer
    bn_finalize<<<1, 256>>>(g_1, be_1, W2_1, b2_1);
    gemm64<64, true, true, true><<<gemm_blocks, 256>>>(zA, W2p, b2p, hout, NN, batch, xg);
}